// round 12
// baseline (speedup 1.0000x reference)
#include <cuda_runtime.h>
#include <cuda_bf16.h>
#include <math.h>

// Problem constants
#define N_TOK   16384
#define DM      4096
#define NE      64
#define TOPK    2
#define CAP     308          // ceil(1.2 * 16384 / 64)
#define M_SLOTS (N_TOK * TOPK)   // 32768
#define MAXB    32768        // per-expert bucket capacity (worst case = all slots)

// Output layout (float32, concatenated reference tuple):
//   [0, 32768)        topk_ids (as float)
//   [32768, 65536)    topk_gates
//   [65536]           aux_loss
//   [65537, 98305)    mask (0/1 float)
#define OUT_IDS   0
#define OUT_GATES (M_SLOTS)
#define OUT_AUX   (2 * M_SLOTS)
#define OUT_MASK  (2 * M_SLOTS + 1)

// ---------------- device scratch (no allocations allowed) ----------------
__device__ float g_logits[N_TOK * NE];        // 4 MB
__device__ float g_imp[NE];
__device__ int   g_cnt[NE];
__device__ int   g_load[NE];
__device__ float g_bgate[NE * MAXB];          // 8 MB
__device__ int   g_bidx [NE * MAXB];          // 8 MB
__device__ unsigned char g_keep[M_SLOTS];

// ---------------- init: zero counters ----------------
__global__ void init_kernel() {
    int t = threadIdx.x;
    if (t < NE) { g_cnt[t] = 0; g_imp[t] = 0.f; }
}

// ---------------- GEMM: logits = x @ W^T + b ----------------
// BM=128 tokens, BN=64 experts (all), BK=32. 256 threads, 8x4 per-thread tile.
#define BM 128
#define BN 64
#define BK 32

__global__ __launch_bounds__(256, 2)
void gemm_kernel(const float* __restrict__ A,   // [N_TOK, DM]
                 const float* __restrict__ W,   // [NE, DM]
                 const float* __restrict__ bias)
{
    __shared__ float As[BK][BM + 4];   // transposed, padded
    __shared__ float Bs[BK][BN + 4];

    const int tid = threadIdx.x;
    const int block_m = blockIdx.x * BM;
    const int tx = tid & 15;           // n: 16 * 4 = 64
    const int ty = tid >> 4;           // m: 16 * 8 = 128

    float acc[8][4];
#pragma unroll
    for (int i = 0; i < 8; i++)
#pragma unroll
        for (int j = 0; j < 4; j++) acc[i][j] = 0.f;

    for (int k0 = 0; k0 < DM; k0 += BK) {
        // A tile: 128x32 floats = 1024 float4; 4 per thread
#pragma unroll
        for (int l = 0; l < 4; l++) {
            int q = tid + l * 256;
            int r = q >> 3;
            int c = (q & 7) * 4;
            float4 v = *(const float4*)(A + (size_t)(block_m + r) * DM + k0 + c);
            As[c + 0][r] = v.x; As[c + 1][r] = v.y;
            As[c + 2][r] = v.z; As[c + 3][r] = v.w;
        }
        // B tile: W[64][32] = 512 float4; 2 per thread (Bs[k][n] = W[n][k0+k])
#pragma unroll
        for (int l = 0; l < 2; l++) {
            int q = tid + l * 256;
            int n = q >> 3;
            int c = (q & 7) * 4;
            float4 v = *(const float4*)(W + (size_t)n * DM + k0 + c);
            Bs[c + 0][n] = v.x; Bs[c + 1][n] = v.y;
            Bs[c + 2][n] = v.z; Bs[c + 3][n] = v.w;
        }
        __syncthreads();

#pragma unroll
        for (int kk = 0; kk < BK; kk++) {
            float a[8], bb[4];
            *(float4*)(a)     = *(const float4*)&As[kk][ty * 8];
            *(float4*)(a + 4) = *(const float4*)&As[kk][ty * 8 + 4];
            *(float4*)(bb)    = *(const float4*)&Bs[kk][tx * 4];
#pragma unroll
            for (int i = 0; i < 8; i++)
#pragma unroll
                for (int j = 0; j < 4; j++)
                    acc[i][j] = fmaf(a[i], bb[j], acc[i][j]);
        }
        __syncthreads();
    }

    // epilogue: add bias, write logits
    float b4[4];
    *(float4*)b4 = *(const float4*)(bias + tx * 4);
#pragma unroll
    for (int i = 0; i < 8; i++) {
        int m = block_m + ty * 8 + i;
        float4 o;
        o.x = acc[i][0] + b4[0];
        o.y = acc[i][1] + b4[1];
        o.z = acc[i][2] + b4[2];
        o.w = acc[i][3] + b4[3];
        *(float4*)(g_logits + (size_t)m * NE + tx * 4) = o;
    }
}

// ---------------- softmax + top-2 + scatter + importance ----------------
// 256 threads = 8 warps; each warp handles 4 tokens -> 32 tokens/block.
__device__ __forceinline__ bool better(float av, int ai, float bv, int bi) {
    return (av > bv) || (av == bv && ai < bi);
}

__global__ void route_kernel(float* __restrict__ out) {
    __shared__ float s_imp[NE];
    const int tid = threadIdx.x;
    if (tid < NE) s_imp[tid] = 0.f;
    __syncthreads();

    const int warp = tid >> 5;
    const int lane = tid & 31;
    const int tok0 = blockIdx.x * 32 + warp * 4;

    for (int t = tok0; t < tok0 + 4; t++) {
        float l0 = g_logits[(size_t)t * NE + lane];
        float l1 = g_logits[(size_t)t * NE + 32 + lane];

        // softmax (exp(l - max) / sum)
        float m = fmaxf(l0, l1);
#pragma unroll
        for (int o = 16; o; o >>= 1) m = fmaxf(m, __shfl_xor_sync(0xffffffffu, m, o));
        float e0 = expf(l0 - m), e1 = expf(l1 - m);
        float s = e0 + e1;
#pragma unroll
        for (int o = 16; o; o >>= 1) s += __shfl_xor_sync(0xffffffffu, s, o);
        float p0 = e0 / s, p1 = e1 / s;

        // importance accumulation
        atomicAdd(&s_imp[lane], p0);
        atomicAdd(&s_imp[lane + 32], p1);

        // per-lane ordered pair (tie: lower index first)
        float v1, v2; int i1, i2;
        if (p0 >= p1) { v1 = p0; i1 = lane;      v2 = p1; i2 = lane + 32; }
        else          { v1 = p1; i1 = lane + 32; v2 = p0; i2 = lane;      }

        // warp butterfly top-2 merge
#pragma unroll
        for (int o = 16; o; o >>= 1) {
            float w1 = __shfl_xor_sync(0xffffffffu, v1, o);
            float w2 = __shfl_xor_sync(0xffffffffu, v2, o);
            int   j1 = __shfl_xor_sync(0xffffffffu, i1, o);
            int   j2 = __shfl_xor_sync(0xffffffffu, i2, o);
            if (better(w1, j1, v1, i1)) {
                bool k = better(v1, i1, w2, j2);
                v2 = k ? v1 : w2; i2 = k ? i1 : j2;
                v1 = w1; i1 = j1;
            } else {
                bool k = better(w1, j1, v2, i2);
                v2 = k ? w1 : v2; i2 = k ? j1 : i2;
            }
        }

        if (lane == 0) {
            out[OUT_IDS   + t * 2 + 0] = (float)i1;
            out[OUT_IDS   + t * 2 + 1] = (float)i2;
            out[OUT_GATES + t * 2 + 0] = v1;
            out[OUT_GATES + t * 2 + 1] = v2;

            int p = atomicAdd(&g_cnt[i1], 1);
            g_bgate[i1 * MAXB + p] = v1;
            g_bidx [i1 * MAXB + p] = t * 2 + 0;
            p = atomicAdd(&g_cnt[i2], 1);
            g_bgate[i2 * MAXB + p] = v2;
            g_bidx [i2 * MAXB + p] = t * 2 + 1;
        }
    }

    __syncthreads();
    if (tid < NE) atomicAdd(&g_imp[tid], s_imp[tid]);
}

// ---------------- per-expert capacity ranking ----------------
// keep slot iff #{j same expert : gate_j > gate_i || (gate_j==gate_i && idx_j<idx_i)} < CAP
#define RCHUNK 1024
__global__ void rank_kernel() {
    const int e = blockIdx.x;
    const int n = g_cnt[e];
    const float* __restrict__ bg = g_bgate + (size_t)e * MAXB;
    const int*   __restrict__ bi = g_bidx  + (size_t)e * MAXB;

    __shared__ float sg[RCHUNK];
    __shared__ int   si[RCHUNK];

    for (int ib = 0; ib < n; ib += 256) {
        int i = ib + threadIdx.x;
        bool valid = (i < n);
        float gi = 0.f; int xi = 0;
        if (valid) { gi = bg[i]; xi = bi[i]; }
        int r = 0;
        for (int jb = 0; jb < n; jb += RCHUNK) {
            int cn = min(RCHUNK, n - jb);
            __syncthreads();
            for (int j = threadIdx.x; j < cn; j += 256) {
                sg[j] = bg[jb + j];
                si[j] = bi[jb + j];
            }
            __syncthreads();
            if (valid) {
                for (int j = 0; j < cn; j++) {
                    float gj = sg[j];
                    r += (gj > gi) || (gj == gi && si[j] < xi);
                }
            }
        }
        if (valid) g_keep[xi] = (r < CAP) ? 1 : 0;
    }
    if (threadIdx.x == 0) g_load[e] = (n < CAP) ? n : CAP;
}

// ---------------- finalize: mask + aux loss ----------------
__global__ void final_kernel(float* __restrict__ out) {
    int s = blockIdx.x * 256 + threadIdx.x;
    if (s < M_SLOTS) out[OUT_MASK + s] = (float)g_keep[s];
    if (blockIdx.x == 0 && threadIdx.x == 0) {
        float aux = 0.f;
        const float Nf = (float)N_TOK;
        for (int e = 0; e < NE; e++)
            aux += (float)NE * (g_imp[e] / Nf) * ((float)g_load[e] / Nf);
        out[OUT_AUX] = aux;
    }
}

// ---------------- launch ----------------
extern "C" void kernel_launch(void* const* d_in, const int* in_sizes, int n_in,
                              void* d_out, int out_size) {
    (void)in_sizes; (void)n_in; (void)out_size;
    const float* x = (const float*)d_in[0];   // [16384, 4096]
    const float* W = (const float*)d_in[1];   // [64, 4096]
    const float* b = (const float*)d_in[2];   // [64]
    float* out = (float*)d_out;

    init_kernel<<<1, 128>>>();
    gemm_kernel<<<N_TOK / BM, 256>>>(x, W, b);
    route_kernel<<<N_TOK / 32, 256>>>(out);
    rank_kernel<<<NE, 256>>>();
    final_kernel<<<(M_SLOTS + 255) / 256, 256>>>(out);
}

// round 13
// speedup vs baseline: 1.0054x; 1.0054x over previous
#include <cuda_runtime.h>
#include <cuda_bf16.h>
#include <math.h>

// Problem constants
#define N_TOK   16384
#define DM      4096
#define NE      64
#define TOPK    2
#define CAP     308          // ceil(1.2 * 16384 / 64)
#define M_SLOTS (N_TOK * TOPK)   // 32768
#define MAXB    32768        // per-expert bucket capacity (worst case = all slots)

// Output layout (float32, concatenated reference tuple):
//   [0, 32768)        topk_ids (as float)
//   [32768, 65536)    topk_gates
//   [65536]           aux_loss
//   [65537, 98305)    mask (0/1 float)
#define OUT_IDS   0
#define OUT_GATES (M_SLOTS)
#define OUT_AUX   (2 * M_SLOTS)
#define OUT_MASK  (2 * M_SLOTS + 1)

// ---------------- device scratch (no allocations allowed) ----------------
__device__ float g_logits[N_TOK * NE];        // 4 MB
__device__ float g_imp[NE];
__device__ int   g_cnt[NE];
__device__ int   g_load[NE];
__device__ float g_bgate[NE * MAXB];          // 8 MB
__device__ int   g_bidx [NE * MAXB];          // 8 MB
__device__ unsigned char g_keep[M_SLOTS];

// ---------------- init: zero counters ----------------
__global__ void init_kernel() {
    int t = threadIdx.x;
    if (t < NE) { g_cnt[t] = 0; g_imp[t] = 0.f; }
}

// ---------------- GEMM: logits = x @ W^T + b ----------------
// BM=128 tokens, BN=64 experts (all), BK=32. 256 threads, 8x4 per-thread tile.
#define BM 128
#define BN 64
#define BK 32

__global__ __launch_bounds__(256, 2)
void gemm_kernel(const float* __restrict__ A,   // [N_TOK, DM]
                 const float* __restrict__ W,   // [NE, DM]
                 const float* __restrict__ bias)
{
    __shared__ float As[BK][BM + 4];   // transposed, padded
    __shared__ float Bs[BK][BN + 4];

    const int tid = threadIdx.x;
    const int block_m = blockIdx.x * BM;
    const int tx = tid & 15;           // n: 16 * 4 = 64
    const int ty = tid >> 4;           // m: 16 * 8 = 128

    float acc[8][4];
#pragma unroll
    for (int i = 0; i < 8; i++)
#pragma unroll
        for (int j = 0; j < 4; j++) acc[i][j] = 0.f;

    for (int k0 = 0; k0 < DM; k0 += BK) {
        // A tile: 128x32 floats = 1024 float4; 4 per thread
#pragma unroll
        for (int l = 0; l < 4; l++) {
            int q = tid + l * 256;
            int r = q >> 3;
            int c = (q & 7) * 4;
            float4 v = *(const float4*)(A + (size_t)(block_m + r) * DM + k0 + c);
            As[c + 0][r] = v.x; As[c + 1][r] = v.y;
            As[c + 2][r] = v.z; As[c + 3][r] = v.w;
        }
        // B tile: W[64][32] = 512 float4; 2 per thread (Bs[k][n] = W[n][k0+k])
#pragma unroll
        for (int l = 0; l < 2; l++) {
            int q = tid + l * 256;
            int n = q >> 3;
            int c = (q & 7) * 4;
            float4 v = *(const float4*)(W + (size_t)n * DM + k0 + c);
            Bs[c + 0][n] = v.x; Bs[c + 1][n] = v.y;
            Bs[c + 2][n] = v.z; Bs[c + 3][n] = v.w;
        }
        __syncthreads();

#pragma unroll
        for (int kk = 0; kk < BK; kk++) {
            float a[8], bb[4];
            *(float4*)(a)     = *(const float4*)&As[kk][ty * 8];
            *(float4*)(a + 4) = *(const float4*)&As[kk][ty * 8 + 4];
            *(float4*)(bb)    = *(const float4*)&Bs[kk][tx * 4];
#pragma unroll
            for (int i = 0; i < 8; i++)
#pragma unroll
                for (int j = 0; j < 4; j++)
                    acc[i][j] = fmaf(a[i], bb[j], acc[i][j]);
        }
        __syncthreads();
    }

    // epilogue: add bias, write logits
    float b4[4];
    *(float4*)b4 = *(const float4*)(bias + tx * 4);
#pragma unroll
    for (int i = 0; i < 8; i++) {
        int m = block_m + ty * 8 + i;
        float4 o;
        o.x = acc[i][0] + b4[0];
        o.y = acc[i][1] + b4[1];
        o.z = acc[i][2] + b4[2];
        o.w = acc[i][3] + b4[3];
        *(float4*)(g_logits + (size_t)m * NE + tx * 4) = o;
    }
}

// ---------------- softmax + top-2 + scatter + importance ----------------
// 256 threads = 8 warps; each warp handles 4 tokens -> 32 tokens/block.
__device__ __forceinline__ bool better(float av, int ai, float bv, int bi) {
    return (av > bv) || (av == bv && ai < bi);
}

__global__ void route_kernel(float* __restrict__ out) {
    __shared__ float s_imp[NE];
    const int tid = threadIdx.x;
    if (tid < NE) s_imp[tid] = 0.f;
    __syncthreads();

    const int warp = tid >> 5;
    const int lane = tid & 31;
    const int tok0 = blockIdx.x * 32 + warp * 4;

    for (int t = tok0; t < tok0 + 4; t++) {
        float l0 = g_logits[(size_t)t * NE + lane];
        float l1 = g_logits[(size_t)t * NE + 32 + lane];

        // softmax (exp(l - max) / sum)
        float m = fmaxf(l0, l1);
#pragma unroll
        for (int o = 16; o; o >>= 1) m = fmaxf(m, __shfl_xor_sync(0xffffffffu, m, o));
        float e0 = expf(l0 - m), e1 = expf(l1 - m);
        float s = e0 + e1;
#pragma unroll
        for (int o = 16; o; o >>= 1) s += __shfl_xor_sync(0xffffffffu, s, o);
        float p0 = e0 / s, p1 = e1 / s;

        // importance accumulation
        atomicAdd(&s_imp[lane], p0);
        atomicAdd(&s_imp[lane + 32], p1);

        // per-lane ordered pair (tie: lower index first)
        float v1, v2; int i1, i2;
        if (p0 >= p1) { v1 = p0; i1 = lane;      v2 = p1; i2 = lane + 32; }
        else          { v1 = p1; i1 = lane + 32; v2 = p0; i2 = lane;      }

        // warp butterfly top-2 merge
#pragma unroll
        for (int o = 16; o; o >>= 1) {
            float w1 = __shfl_xor_sync(0xffffffffu, v1, o);
            float w2 = __shfl_xor_sync(0xffffffffu, v2, o);
            int   j1 = __shfl_xor_sync(0xffffffffu, i1, o);
            int   j2 = __shfl_xor_sync(0xffffffffu, i2, o);
            if (better(w1, j1, v1, i1)) {
                bool k = better(v1, i1, w2, j2);
                v2 = k ? v1 : w2; i2 = k ? i1 : j2;
                v1 = w1; i1 = j1;
            } else {
                bool k = better(w1, j1, v2, i2);
                v2 = k ? w1 : v2; i2 = k ? j1 : i2;
            }
        }

        if (lane == 0) {
            out[OUT_IDS   + t * 2 + 0] = (float)i1;
            out[OUT_IDS   + t * 2 + 1] = (float)i2;
            out[OUT_GATES + t * 2 + 0] = v1;
            out[OUT_GATES + t * 2 + 1] = v2;

            int p = atomicAdd(&g_cnt[i1], 1);
            g_bgate[i1 * MAXB + p] = v1;
            g_bidx [i1 * MAXB + p] = t * 2 + 0;
            p = atomicAdd(&g_cnt[i2], 1);
            g_bgate[i2 * MAXB + p] = v2;
            g_bidx [i2 * MAXB + p] = t * 2 + 1;
        }
    }

    __syncthreads();
    if (tid < NE) atomicAdd(&g_imp[tid], s_imp[tid]);
}

// ---------------- per-expert capacity ranking ----------------
// keep slot iff #{j same expert : gate_j > gate_i || (gate_j==gate_i && idx_j<idx_i)} < CAP
#define RCHUNK 1024
__global__ void rank_kernel() {
    const int e = blockIdx.x;
    const int n = g_cnt[e];
    const float* __restrict__ bg = g_bgate + (size_t)e * MAXB;
    const int*   __restrict__ bi = g_bidx  + (size_t)e * MAXB;

    __shared__ float sg[RCHUNK];
    __shared__ int   si[RCHUNK];

    for (int ib = 0; ib < n; ib += 256) {
        int i = ib + threadIdx.x;
        bool valid = (i < n);
        float gi = 0.f; int xi = 0;
        if (valid) { gi = bg[i]; xi = bi[i]; }
        int r = 0;
        for (int jb = 0; jb < n; jb += RCHUNK) {
            int cn = min(RCHUNK, n - jb);
            __syncthreads();
            for (int j = threadIdx.x; j < cn; j += 256) {
                sg[j] = bg[jb + j];
                si[j] = bi[jb + j];
            }
            __syncthreads();
            if (valid) {
                for (int j = 0; j < cn; j++) {
                    float gj = sg[j];
                    r += (gj > gi) || (gj == gi && si[j] < xi);
                }
            }
        }
        if (valid) g_keep[xi] = (r < CAP) ? 1 : 0;
    }
    if (threadIdx.x == 0) g_load[e] = (n < CAP) ? n : CAP;
}

// ---------------- finalize: mask + aux loss ----------------
__global__ void final_kernel(float* __restrict__ out) {
    int s = blockIdx.x * 256 + threadIdx.x;
    if (s < M_SLOTS) out[OUT_MASK + s] = (float)g_keep[s];
    if (blockIdx.x == 0 && threadIdx.x == 0) {
        float aux = 0.f;
        const float Nf = (float)N_TOK;
        for (int e = 0; e < NE; e++)
            aux += (float)NE * (g_imp[e] / Nf) * ((float)g_load[e] / Nf);
        out[OUT_AUX] = aux;
    }
}

// ---------------- launch ----------------
extern "C" void kernel_launch(void* const* d_in, const int* in_sizes, int n_in,
                              void* d_out, int out_size) {
    (void)in_sizes; (void)n_in; (void)out_size;
    const float* x = (const float*)d_in[0];   // [16384, 4096]
    const float* W = (const float*)d_in[1];   // [64, 4096]
    const float* b = (const float*)d_in[2];   // [64]
    float* out = (float*)d_out;

    init_kernel<<<1, 128>>>();
    gemm_kernel<<<N_TOK / BM, 256>>>(x, W, b);
    route_kernel<<<N_TOK / 32, 256>>>(out);
    rank_kernel<<<NE, 256>>>();
    final_kernel<<<(M_SLOTS + 255) / 256, 256>>>(out);
}

// round 14
// speedup vs baseline: 1.0054x; 1.0001x over previous
#include <cuda_runtime.h>
#include <cuda_bf16.h>
#include <math.h>

// Problem constants
#define N_TOK   16384
#define DM      4096
#define NE      64
#define TOPK    2
#define CAP     308          // ceil(1.2 * 16384 / 64)
#define M_SLOTS (N_TOK * TOPK)   // 32768
#define MAXB    32768        // per-expert bucket capacity (worst case = all slots)

// Output layout (float32, concatenated reference tuple):
//   [0, 32768)        topk_ids (as float)
//   [32768, 65536)    topk_gates
//   [65536]           aux_loss
//   [65537, 98305)    mask (0/1 float)
#define OUT_IDS   0
#define OUT_GATES (M_SLOTS)
#define OUT_AUX   (2 * M_SLOTS)
#define OUT_MASK  (2 * M_SLOTS + 1)

// ---------------- device scratch (no allocations allowed) ----------------
__device__ float g_logits[N_TOK * NE];        // 4 MB
__device__ float g_imp[NE];
__device__ int   g_cnt[NE];
__device__ int   g_load[NE];
__device__ float g_bgate[NE * MAXB];          // 8 MB
__device__ int   g_bidx [NE * MAXB];          // 8 MB
__device__ unsigned char g_keep[M_SLOTS];

// ---------------- init: zero counters ----------------
__global__ void init_kernel() {
    int t = threadIdx.x;
    if (t < NE) { g_cnt[t] = 0; g_imp[t] = 0.f; }
}

// ---------------- GEMM: logits = x @ W^T + b ----------------
// BM=128 tokens, BN=64 experts (all), BK=32. 256 threads, 8x4 per-thread tile.
#define BM 128
#define BN 64
#define BK 32

__global__ __launch_bounds__(256, 2)
void gemm_kernel(const float* __restrict__ A,   // [N_TOK, DM]
                 const float* __restrict__ W,   // [NE, DM]
                 const float* __restrict__ bias)
{
    __shared__ float As[BK][BM + 4];   // transposed, padded
    __shared__ float Bs[BK][BN + 4];

    const int tid = threadIdx.x;
    const int block_m = blockIdx.x * BM;
    const int tx = tid & 15;           // n: 16 * 4 = 64
    const int ty = tid >> 4;           // m: 16 * 8 = 128

    float acc[8][4];
#pragma unroll
    for (int i = 0; i < 8; i++)
#pragma unroll
        for (int j = 0; j < 4; j++) acc[i][j] = 0.f;

    for (int k0 = 0; k0 < DM; k0 += BK) {
        // A tile: 128x32 floats = 1024 float4; 4 per thread
#pragma unroll
        for (int l = 0; l < 4; l++) {
            int q = tid + l * 256;
            int r = q >> 3;
            int c = (q & 7) * 4;
            float4 v = *(const float4*)(A + (size_t)(block_m + r) * DM + k0 + c);
            As[c + 0][r] = v.x; As[c + 1][r] = v.y;
            As[c + 2][r] = v.z; As[c + 3][r] = v.w;
        }
        // B tile: W[64][32] = 512 float4; 2 per thread (Bs[k][n] = W[n][k0+k])
#pragma unroll
        for (int l = 0; l < 2; l++) {
            int q = tid + l * 256;
            int n = q >> 3;
            int c = (q & 7) * 4;
            float4 v = *(const float4*)(W + (size_t)n * DM + k0 + c);
            Bs[c + 0][n] = v.x; Bs[c + 1][n] = v.y;
            Bs[c + 2][n] = v.z; Bs[c + 3][n] = v.w;
        }
        __syncthreads();

#pragma unroll
        for (int kk = 0; kk < BK; kk++) {
            float a[8], bb[4];
            *(float4*)(a)     = *(const float4*)&As[kk][ty * 8];
            *(float4*)(a + 4) = *(const float4*)&As[kk][ty * 8 + 4];
            *(float4*)(bb)    = *(const float4*)&Bs[kk][tx * 4];
#pragma unroll
            for (int i = 0; i < 8; i++)
#pragma unroll
                for (int j = 0; j < 4; j++)
                    acc[i][j] = fmaf(a[i], bb[j], acc[i][j]);
        }
        __syncthreads();
    }

    // epilogue: add bias, write logits
    float b4[4];
    *(float4*)b4 = *(const float4*)(bias + tx * 4);
#pragma unroll
    for (int i = 0; i < 8; i++) {
        int m = block_m + ty * 8 + i;
        float4 o;
        o.x = acc[i][0] + b4[0];
        o.y = acc[i][1] + b4[1];
        o.z = acc[i][2] + b4[2];
        o.w = acc[i][3] + b4[3];
        *(float4*)(g_logits + (size_t)m * NE + tx * 4) = o;
    }
}

// ---------------- softmax + top-2 + scatter + importance ----------------
// 256 threads = 8 warps; each warp handles 4 tokens -> 32 tokens/block.
__device__ __forceinline__ bool better(float av, int ai, float bv, int bi) {
    return (av > bv) || (av == bv && ai < bi);
}

__global__ void route_kernel(float* __restrict__ out) {
    __shared__ float s_imp[NE];
    const int tid = threadIdx.x;
    if (tid < NE) s_imp[tid] = 0.f;
    __syncthreads();

    const int warp = tid >> 5;
    const int lane = tid & 31;
    const int tok0 = blockIdx.x * 32 + warp * 4;

    for (int t = tok0; t < tok0 + 4; t++) {
        float l0 = g_logits[(size_t)t * NE + lane];
        float l1 = g_logits[(size_t)t * NE + 32 + lane];

        // softmax (exp(l - max) / sum)
        float m = fmaxf(l0, l1);
#pragma unroll
        for (int o = 16; o; o >>= 1) m = fmaxf(m, __shfl_xor_sync(0xffffffffu, m, o));
        float e0 = expf(l0 - m), e1 = expf(l1 - m);
        float s = e0 + e1;
#pragma unroll
        for (int o = 16; o; o >>= 1) s += __shfl_xor_sync(0xffffffffu, s, o);
        float p0 = e0 / s, p1 = e1 / s;

        // importance accumulation
        atomicAdd(&s_imp[lane], p0);
        atomicAdd(&s_imp[lane + 32], p1);

        // per-lane ordered pair (tie: lower index first)
        float v1, v2; int i1, i2;
        if (p0 >= p1) { v1 = p0; i1 = lane;      v2 = p1; i2 = lane + 32; }
        else          { v1 = p1; i1 = lane + 32; v2 = p0; i2 = lane;      }

        // warp butterfly top-2 merge
#pragma unroll
        for (int o = 16; o; o >>= 1) {
            float w1 = __shfl_xor_sync(0xffffffffu, v1, o);
            float w2 = __shfl_xor_sync(0xffffffffu, v2, o);
            int   j1 = __shfl_xor_sync(0xffffffffu, i1, o);
            int   j2 = __shfl_xor_sync(0xffffffffu, i2, o);
            if (better(w1, j1, v1, i1)) {
                bool k = better(v1, i1, w2, j2);
                v2 = k ? v1 : w2; i2 = k ? i1 : j2;
                v1 = w1; i1 = j1;
            } else {
                bool k = better(w1, j1, v2, i2);
                v2 = k ? w1 : v2; i2 = k ? j1 : i2;
            }
        }

        if (lane == 0) {
            out[OUT_IDS   + t * 2 + 0] = (float)i1;
            out[OUT_IDS   + t * 2 + 1] = (float)i2;
            out[OUT_GATES + t * 2 + 0] = v1;
            out[OUT_GATES + t * 2 + 1] = v2;

            int p = atomicAdd(&g_cnt[i1], 1);
            g_bgate[i1 * MAXB + p] = v1;
            g_bidx [i1 * MAXB + p] = t * 2 + 0;
            p = atomicAdd(&g_cnt[i2], 1);
            g_bgate[i2 * MAXB + p] = v2;
            g_bidx [i2 * MAXB + p] = t * 2 + 1;
        }
    }

    __syncthreads();
    if (tid < NE) atomicAdd(&g_imp[tid], s_imp[tid]);
}

// ---------------- per-expert capacity ranking ----------------
// keep slot iff #{j same expert : gate_j > gate_i || (gate_j==gate_i && idx_j<idx_i)} < CAP
#define RCHUNK 1024
__global__ void rank_kernel() {
    const int e = blockIdx.x;
    const int n = g_cnt[e];
    const float* __restrict__ bg = g_bgate + (size_t)e * MAXB;
    const int*   __restrict__ bi = g_bidx  + (size_t)e * MAXB;

    __shared__ float sg[RCHUNK];
    __shared__ int   si[RCHUNK];

    for (int ib = 0; ib < n; ib += 256) {
        int i = ib + threadIdx.x;
        bool valid = (i < n);
        float gi = 0.f; int xi = 0;
        if (valid) { gi = bg[i]; xi = bi[i]; }
        int r = 0;
        for (int jb = 0; jb < n; jb += RCHUNK) {
            int cn = min(RCHUNK, n - jb);
            __syncthreads();
            for (int j = threadIdx.x; j < cn; j += 256) {
                sg[j] = bg[jb + j];
                si[j] = bi[jb + j];
            }
            __syncthreads();
            if (valid) {
                for (int j = 0; j < cn; j++) {
                    float gj = sg[j];
                    r += (gj > gi) || (gj == gi && si[j] < xi);
                }
            }
        }
        if (valid) g_keep[xi] = (r < CAP) ? 1 : 0;
    }
    if (threadIdx.x == 0) g_load[e] = (n < CAP) ? n : CAP;
}

// ---------------- finalize: mask + aux loss ----------------
__global__ void final_kernel(float* __restrict__ out) {
    int s = blockIdx.x * 256 + threadIdx.x;
    if (s < M_SLOTS) out[OUT_MASK + s] = (float)g_keep[s];
    if (blockIdx.x == 0 && threadIdx.x == 0) {
        float aux = 0.f;
        const float Nf = (float)N_TOK;
        for (int e = 0; e < NE; e++)
            aux += (float)NE * (g_imp[e] / Nf) * ((float)g_load[e] / Nf);
        out[OUT_AUX] = aux;
    }
}

// ---------------- launch ----------------
extern "C" void kernel_launch(void* const* d_in, const int* in_sizes, int n_in,
                              void* d_out, int out_size) {
    (void)in_sizes; (void)n_in; (void)out_size;
    const float* x = (const float*)d_in[0];   // [16384, 4096]
    const float* W = (const float*)d_in[1];   // [64, 4096]
    const float* b = (const float*)d_in[2];   // [64]
    float* out = (float*)d_out;

    init_kernel<<<1, 128>>>();
    gemm_kernel<<<N_TOK / BM, 256>>>(x, W, b);
    route_kernel<<<N_TOK / 32, 256>>>(out);
    rank_kernel<<<NE, 256>>>();
    final_kernel<<<(M_SLOTS + 255) / 256, 256>>>(out);
}